// round 6
// baseline (speedup 1.0000x reference)
#include <cuda_runtime.h>

#define NN 100000          // nodes
#define DIM 64             // embed dim
#define NE 1600000         // edges
#define NL 100000          // label edges
#define ALPHA 0.25f        // 1/(NLAYERS+1), NLAYERS=3
#define SCAN_B 1024
#define NB ((NN + SCAN_B - 1) / SCAN_B)   // 98 scan blocks

// ---- MLP tiling: 128 edges per block, thread tile = 8 hidden x 4 edges ----
#define MTILE 128
#define N_MTILES ((NL + MTILE - 1) / MTILE)   // 782
#define EPAD 132           // padded edge dimension of transposed input tile

// dynamic smem layout (floats):
// W1[8192] | sInT[128*EPAD] | b1[64] | W2[64] | sS[128 int] | sD[128 int]
#define SM_W1   0
#define SM_IN   8192
#define SM_B1   (SM_IN + 128 * EPAD)
#define SM_W2   (SM_B1 + 64)
#define SM_S    (SM_W2 + 64)
#define SM_D    (SM_S + 128)
#define SM_TOT  (SM_D + 128)               // 25472 floats = 101888 bytes

// ---------------- scratch (device globals; no allocation allowed) -------------
__device__ int   g_cnt[NN];            // int degree / fill counters
__device__ float g_dinv[NN];           // deg^-1/2
__device__ int   g_rowptr[NN + 1];     // CSR row pointers (by dst)
__device__ int   g_bsum[NB];           // scan block sums
__device__ int   g_csr_src[NE];        // CSR column indices (src nodes)
__device__ float g_A[NN * DIM];        // ping (pre-scaled y)
__device__ float g_B[NN * DIM];        // pong
__device__ float g_out[NN * DIM];      // LightGCN accumulated embedding
__device__ float g_pred[NL];           // MLP predictions

// ---------------- degree ------------------------------------------------------
__global__ void zero_cnt_kernel() {
    int i = blockIdx.x * blockDim.x + threadIdx.x;
    if (i < NN) g_cnt[i] = 0;
}

__global__ void deg_kernel(const int* __restrict__ dst) {
    int e = blockIdx.x * blockDim.x + threadIdx.x;
    if (e < NE) atomicAdd(&g_cnt[dst[e]], 1);
}

// ---------------- CSR build: prefix sum (+dinv fused) + fill -------------------
__global__ void scan_block_kernel() {
    __shared__ int sh[SCAN_B];
    int i = blockIdx.x * SCAN_B + threadIdx.x;
    int v = (i < NN) ? g_cnt[i] : 0;
    if (i < NN) g_dinv[i] = (v > 0) ? rsqrtf((float)v) : 0.0f;   // fused dinv
    sh[threadIdx.x] = v;
    __syncthreads();
#pragma unroll
    for (int off = 1; off < SCAN_B; off <<= 1) {
        int t = 0;
        if (threadIdx.x >= off) t = sh[threadIdx.x - off];
        __syncthreads();
        if (threadIdx.x >= off) sh[threadIdx.x] += t;
        __syncthreads();
    }
    if (i < NN) g_rowptr[i] = sh[threadIdx.x] - v;   // exclusive within block
    if (threadIdx.x == SCAN_B - 1) g_bsum[blockIdx.x] = sh[SCAN_B - 1];
}

__global__ void scan_bsum_kernel() {
    if (threadIdx.x == 0 && blockIdx.x == 0) {
        int acc = 0;
        for (int i = 0; i < NB; i++) { int v = g_bsum[i]; g_bsum[i] = acc; acc += v; }
    }
}

__global__ void add_offset_kernel() {
    int i = blockIdx.x * blockDim.x + threadIdx.x;
    if (i < NN) {
        g_rowptr[i] += g_bsum[i >> 10];
        g_cnt[i] = 0;                    // fused re-zero for fill phase
    }
    if (i == 0) g_rowptr[NN] = NE;
}

__global__ void fill_csr_kernel(const int* __restrict__ src, const int* __restrict__ dst) {
    int e = blockIdx.x * blockDim.x + threadIdx.x;
    if (e < NE) {
        int d = dst[e];
        int pos = atomicAdd(&g_cnt[d], 1);
        g_csr_src[g_rowptr[d] + pos] = src[e];
    }
}

// ---------------- init: out = alpha*emb; y0 = dinv * emb ----------------------
__global__ void init_kernel(const float* __restrict__ emb, float* __restrict__ y) {
    int i = blockIdx.x * blockDim.x + threadIdx.x;   // float4 index
    if (i >= NN * (DIM / 4)) return;
    int n = i >> 4;
    float di = __ldg(g_dinv + n);
    float4 v = reinterpret_cast<const float4*>(emb)[i];
    float4 o = {v.x * ALPHA, v.y * ALPHA, v.z * ALPHA, v.w * ALPHA};
    reinterpret_cast<float4*>(g_out)[i] = o;
    float4 s = {v.x * di, v.y * di, v.z * di, v.w * di};
    reinterpret_cast<float4*>(y)[i] = s;
}

// ---------------- gather layer ------------------------------------------------
// 16 lanes per node; lane owns one float4 column chunk. Edge loop unrolled x8.
__global__ void __launch_bounds__(256) gather_kernel(const float* __restrict__ y,
                                                     float* __restrict__ ynext,
                                                     int write_next) {
    int idx = blockIdx.x * blockDim.x + threadIdx.x;
    int n = idx >> 4;
    if (n >= NN) return;
    int lane4 = (idx & 15) << 2;   // float offset within row

    int beg = __ldg(g_rowptr + n);
    int end = __ldg(g_rowptr + n + 1);

    float4 acc = {0.0f, 0.0f, 0.0f, 0.0f};
    int e = beg;
    for (; e + 8 <= end; e += 8) {
        int s[8];
#pragma unroll
        for (int j = 0; j < 8; j++) s[j] = __ldg(g_csr_src + e + j);
        float4 v[8];
#pragma unroll
        for (int j = 0; j < 8; j++)
            v[j] = *reinterpret_cast<const float4*>(y + ((long long)s[j] << 6) + lane4);
#pragma unroll
        for (int j = 0; j < 8; j++) {
            acc.x += v[j].x; acc.y += v[j].y; acc.z += v[j].z; acc.w += v[j].w;
        }
    }
    for (; e < end; e++) {
        int s = __ldg(g_csr_src + e);
        const float4 v = *reinterpret_cast<const float4*>(y + ((long long)s << 6) + lane4);
        acc.x += v.x; acc.y += v.y; acc.z += v.z; acc.w += v.w;
    }
    float di = __ldg(g_dinv + n);
    float4 x = {acc.x * di, acc.y * di, acc.z * di, acc.w * di};

    long long off = ((long long)n << 6) + lane4;
    float4* po = reinterpret_cast<float4*>(g_out + off);
    float4 o = *po;
    o.x += x.x * ALPHA; o.y += x.y * ALPHA; o.z += x.z * ALPHA; o.w += x.w * ALPHA;
    *po = o;

    if (write_next) {
        float4 yn = {x.x * di, x.y * di, x.z * di, x.w * di};
        *reinterpret_cast<float4*>(ynext + off) = yn;
    }
}

// ---------------- MLP scorer: 128-edge tiles, 8h x 4e register tile -----------
// Transposed input tile sInT[dim][edge]: per dim step the whole thread tile
// needs 2 LDS.128 (W quads) + 1 LDS.128 (4 edges' x) for 32 FFMA.
__global__ void __launch_bounds__(256) mlp_kernel(const int* __restrict__ lsrc,
                           const int* __restrict__ ldst,
                           const float* __restrict__ W1,   // [128,64] row-major
                           const float* __restrict__ b1,   // [64]
                           const float* __restrict__ W2,   // [64]
                           const float* __restrict__ b2,   // [1]
                           float* __restrict__ out, int npred,
                           float* __restrict__ lossp) {
    extern __shared__ float sm[];
    float* sW1  = sm + SM_W1;
    float* sInT = sm + SM_IN;
    float* sB1  = sm + SM_B1;
    float* sW2  = sm + SM_W2;
    int*   sS   = (int*)(sm + SM_S);
    int*   sD   = (int*)(sm + SM_D);

    int t = threadIdx.x;
    int base = blockIdx.x * MTILE;

    if (lossp && blockIdx.x == 0 && t == 0) *lossp = 0.0f;   // zero loss slot

    // cache weights
    for (int k = t; k < 128 * 16; k += 256)
        reinterpret_cast<float4*>(sW1)[k] = reinterpret_cast<const float4*>(W1)[k];
    if (t < 64) { sB1[t] = b1[t]; sW2[t] = W2[t]; }
    if (t < MTILE) {
        int idx = base + t;
        int c = idx < NL ? idx : NL - 1;     // clamp tail (writes guarded later)
        sS[t] = __ldg(lsrc + c);
        sD[t] = __ldg(ldst + c);
    }
    float bias2 = __ldg(b2);
    __syncthreads();

    // gather inputs transposed: work item k -> edge e=k&127, float4-slot q=k>>7
    for (int k = t; k < MTILE * 32; k += 256) {
        int e = k & 127;
        int q = k >> 7;                       // 0..31 (dims 4q..4q+3)
        int node = (q < 16) ? sS[e] : sD[e];
        float4 v = *reinterpret_cast<const float4*>(
            g_out + ((long long)node << 6) + ((q & 15) << 2));
        int dim = q << 2;
        sInT[(dim + 0) * EPAD + e] = v.x;
        sInT[(dim + 1) * EPAD + e] = v.y;
        sInT[(dim + 2) * EPAD + e] = v.z;
        sInT[(dim + 3) * EPAD + e] = v.w;
    }
    __syncthreads();

    // thread tile: h8 = (t&7)*8 hidden, eb = (t>>3)*4 edges
    int h8 = (t & 7) << 3;
    int eb = (t >> 3) << 2;

    float acc[4][8];
#pragma unroll
    for (int e = 0; e < 4; e++)
#pragma unroll
        for (int h = 0; h < 8; h++) acc[e][h] = 0.0f;

#pragma unroll 4
    for (int i = 0; i < 128; i++) {
        const float* w = sW1 + i * 64 + h8;
        float4 wA = *reinterpret_cast<const float4*>(w);
        float4 wB = *reinterpret_cast<const float4*>(w + 4);
        float4 xq = *reinterpret_cast<const float4*>(sInT + i * EPAD + eb);
        float xs[4] = {xq.x, xq.y, xq.z, xq.w};
        float ws[8] = {wA.x, wA.y, wA.z, wA.w, wB.x, wB.y, wB.z, wB.w};
#pragma unroll
        for (int e = 0; e < 4; e++)
#pragma unroll
            for (int h = 0; h < 8; h++)
                acc[e][h] = fmaf(xs[e], ws[h], acc[e][h]);
    }

    // ReLU + W2 dot per edge, then reduce across the 8 hidden-groups (lanes t&7)
#pragma unroll
    for (int e = 0; e < 4; e++) {
        float p = 0.0f;
#pragma unroll
        for (int h = 0; h < 8; h++)
            p += fmaxf(acc[e][h] + sB1[h8 + h], 0.0f) * sW2[h8 + h];
#pragma unroll
        for (int off = 4; off > 0; off >>= 1)
            p += __shfl_down_sync(0xffffffffu, p, off, 8);
        if ((t & 7) == 0) {
            int idx = base + eb + e;
            if (idx < NL) {
                float v = p + bias2;
                g_pred[idx] = v;
                if (idx < npred) out[idx] = v;
            }
        }
    }
}

// ---------------- loss ---------------------------------------------------------
__global__ void loss_kernel(const float* __restrict__ label, float* __restrict__ out_loss) {
    __shared__ float sh[256];
    float acc = 0.0f;
    for (int i = blockIdx.x * blockDim.x + threadIdx.x; i < NL; i += gridDim.x * blockDim.x) {
        float diff = g_pred[i] - label[i];
        acc += diff * diff;
    }
    sh[threadIdx.x] = acc;
    __syncthreads();
    for (int stride = 128; stride > 0; stride >>= 1) {
        if (threadIdx.x < stride) sh[threadIdx.x] += sh[threadIdx.x + stride];
        __syncthreads();
    }
    if (threadIdx.x == 0) atomicAdd(out_loss, sh[0] * (1.0f / NL));
}

// ---------------- host launcher ----------------------------------------------
extern "C" void kernel_launch(void* const* d_in, const int* in_sizes, int n_in,
                              void* d_out, int out_size) {
    const int*   ei   = (const int*)d_in[0];       // [2, NE]
    const int*   eli  = (const int*)d_in[1];       // [2, NL]
    const float* elab = (const float*)d_in[2];     // [NL]
    const float* emb  = (const float*)d_in[3];     // [NN, 64]
    const float* W1   = (const float*)d_in[4];     // [128, 64]
    const float* b1   = (const float*)d_in[5];     // [64]
    const float* W2   = (const float*)d_in[6];     // [64, 1]
    const float* b2   = (const float*)d_in[7];     // [1]
    float* out = (float*)d_out;

    const int* src = ei;
    const int* dst = ei + NE;
    const int* lsrc = eli;
    const int* ldst = eli + NL;

    float *pA, *pB;
    cudaGetSymbolAddress((void**)&pA, g_A);
    cudaGetSymbolAddress((void**)&pB, g_B);

    const int T = 256;
    const int gE  = (NE + T - 1) / T;
    const int gN  = (NN + T - 1) / T;
    const int gI  = (NN * (DIM / 4) + T - 1) / T;  // init (float4 granularity)
    const int gG  = (NN * 16 + T - 1) / T;         // gather (16 lanes/node)
    const int smemBytes = SM_TOT * 4;              // ~99.5 KB dynamic

    static int s_attr_done = 0;
    if (!s_attr_done) {
        cudaFuncSetAttribute(mlp_kernel, cudaFuncAttributeMaxDynamicSharedMemorySize, smemBytes);
        s_attr_done = 1;
    }

    // ---- degree ----
    zero_cnt_kernel<<<gN, T>>>();
    deg_kernel<<<gE, T>>>(dst);

    // ---- CSR build (by dst); dinv fused into scan ----
    scan_block_kernel<<<NB, SCAN_B>>>();
    scan_bsum_kernel<<<1, 32>>>();
    add_offset_kernel<<<gN, T>>>();                // also re-zeros g_cnt
    fill_csr_kernel<<<gE, T>>>(src, dst);

    // ---- LightGCN: out = alpha * sum_l x^(l), pull-style gather layers ----
    init_kernel<<<gI, T>>>(emb, pA);               // out=alpha*emb; A = dinv*emb
    gather_kernel<<<gG, T>>>(pA, pB, 1);           // layer 1: A -> B (pre-scaled)
    gather_kernel<<<gG, T>>>(pB, pA, 1);           // layer 2: B -> A
    gather_kernel<<<gG, T>>>(pA, pB, 0);           // layer 3: out += only

    // ---- scorer MLP (writes g_pred and d_out; block 0 zeros the loss slot) ----
    int npred = out_size < NL ? out_size : NL;
    float* lossp = (out_size != NL) ? out + (out_size - 1) : (float*)0;
    mlp_kernel<<<N_MTILES, 256, smemBytes>>>(lsrc, ldst, W1, b1, W2, b2, out, npred, lossp);

    // ---- loss in the trailing slot (if present) ----
    if (lossp)
        loss_kernel<<<132, 256>>>(elab, lossp);
}

// round 7
// speedup vs baseline: 1.1196x; 1.1196x over previous
#include <cuda_runtime.h>

#define NN 100000          // nodes
#define DIM 64             // embed dim
#define NE 1600000         // edges
#define NL 100000          // label edges
#define ALPHA 0.25f        // 1/(NLAYERS+1), NLAYERS=3
#define SCAN_B 1024
#define NB ((NN + SCAN_B - 1) / SCAN_B)   // 98 scan blocks

// ---- MLP tiling: 64 edges/tile, 256 thr = 16 hgroups x 16 egroups x 4 edges --
#define MTILE 64
#define N_MTILES ((NL + MTILE - 1) / MTILE)   // 1563
#define MLP_BLOCKS 444     // 3 per SM (148 SMs), persistent
#define EPAD 68            // padded edge dimension of transposed input tile

// dynamic smem layout (floats):
// W1[8192] | sInT[128*EPAD] | b1[64] | W2[64] | sS[64 int] | sD[64 int]
#define SM_W1   0
#define SM_IN   8192
#define SM_B1   (SM_IN + 128 * EPAD)
#define SM_W2   (SM_B1 + 64)
#define SM_S    (SM_W2 + 64)
#define SM_D    (SM_S + 64)
#define SM_TOT  (SM_D + 64)                // 17152 floats = 68608 bytes

// ---------------- scratch (device globals; no allocation allowed) -------------
__device__ int   g_cnt[NN];            // int degree / fill counters
__device__ float g_dinv[NN];           // deg^-1/2
__device__ int   g_rowptr[NN + 1];     // CSR row pointers (by dst)
__device__ int   g_bsum[NB];           // scan block sums
__device__ int   g_csr_src[NE];        // CSR column indices (src nodes)
__device__ float g_A[NN * DIM];        // ping (pre-scaled y)
__device__ float g_B[NN * DIM];        // pong
__device__ float g_out[NN * DIM];      // LightGCN accumulated embedding
__device__ float g_pred[NL];           // MLP predictions

// ---------------- degree ------------------------------------------------------
__global__ void zero_cnt_kernel() {
    int i = blockIdx.x * blockDim.x + threadIdx.x;
    if (i < NN) g_cnt[i] = 0;
}

__global__ void deg_kernel(const int* __restrict__ dst) {
    int e = blockIdx.x * blockDim.x + threadIdx.x;
    if (e < NE) atomicAdd(&g_cnt[dst[e]], 1);
}

// ---------------- CSR build: prefix sum (+dinv fused) + fill -------------------
__global__ void scan_block_kernel() {
    __shared__ int sh[SCAN_B];
    int i = blockIdx.x * SCAN_B + threadIdx.x;
    int v = (i < NN) ? g_cnt[i] : 0;
    if (i < NN) g_dinv[i] = (v > 0) ? rsqrtf((float)v) : 0.0f;   // fused dinv
    sh[threadIdx.x] = v;
    __syncthreads();
#pragma unroll
    for (int off = 1; off < SCAN_B; off <<= 1) {
        int t = 0;
        if (threadIdx.x >= off) t = sh[threadIdx.x - off];
        __syncthreads();
        if (threadIdx.x >= off) sh[threadIdx.x] += t;
        __syncthreads();
    }
    if (i < NN) g_rowptr[i] = sh[threadIdx.x] - v;   // exclusive within block
    if (threadIdx.x == SCAN_B - 1) g_bsum[blockIdx.x] = sh[SCAN_B - 1];
}

__global__ void scan_bsum_kernel() {
    if (threadIdx.x == 0 && blockIdx.x == 0) {
        int acc = 0;
        for (int i = 0; i < NB; i++) { int v = g_bsum[i]; g_bsum[i] = acc; acc += v; }
    }
}

__global__ void add_offset_kernel() {
    int i = blockIdx.x * blockDim.x + threadIdx.x;
    if (i < NN) {
        g_rowptr[i] += g_bsum[i >> 10];
        g_cnt[i] = 0;                    // fused re-zero for fill phase
    }
    if (i == 0) g_rowptr[NN] = NE;
}

__global__ void fill_csr_kernel(const int* __restrict__ src, const int* __restrict__ dst) {
    int e = blockIdx.x * blockDim.x + threadIdx.x;
    if (e < NE) {
        int d = dst[e];
        int pos = atomicAdd(&g_cnt[d], 1);
        g_csr_src[g_rowptr[d] + pos] = src[e];
    }
}

// ---------------- init: out = alpha*emb; y0 = dinv * emb ----------------------
__global__ void init_kernel(const float* __restrict__ emb, float* __restrict__ y) {
    int i = blockIdx.x * blockDim.x + threadIdx.x;   // float4 index
    if (i >= NN * (DIM / 4)) return;
    int n = i >> 4;
    float di = __ldg(g_dinv + n);
    float4 v = reinterpret_cast<const float4*>(emb)[i];
    float4 o = {v.x * ALPHA, v.y * ALPHA, v.z * ALPHA, v.w * ALPHA};
    reinterpret_cast<float4*>(g_out)[i] = o;
    float4 s = {v.x * di, v.y * di, v.z * di, v.w * di};
    reinterpret_cast<float4*>(y)[i] = s;
}

// ---------------- gather layer ------------------------------------------------
// 16 lanes per node; lane owns one float4 column chunk. Edge loop unrolled x4
// (the measured-good R5 configuration).
__global__ void __launch_bounds__(256) gather_kernel(const float* __restrict__ y,
                                                     float* __restrict__ ynext,
                                                     int write_next) {
    int idx = blockIdx.x * blockDim.x + threadIdx.x;
    int n = idx >> 4;
    if (n >= NN) return;
    int lane4 = (idx & 15) << 2;   // float offset within row

    int beg = __ldg(g_rowptr + n);
    int end = __ldg(g_rowptr + n + 1);

    float4 acc = {0.0f, 0.0f, 0.0f, 0.0f};
    int e = beg;
    for (; e + 4 <= end; e += 4) {
        int s0 = __ldg(g_csr_src + e + 0);
        int s1 = __ldg(g_csr_src + e + 1);
        int s2 = __ldg(g_csr_src + e + 2);
        int s3 = __ldg(g_csr_src + e + 3);
        float4 v0 = *reinterpret_cast<const float4*>(y + ((long long)s0 << 6) + lane4);
        float4 v1 = *reinterpret_cast<const float4*>(y + ((long long)s1 << 6) + lane4);
        float4 v2 = *reinterpret_cast<const float4*>(y + ((long long)s2 << 6) + lane4);
        float4 v3 = *reinterpret_cast<const float4*>(y + ((long long)s3 << 6) + lane4);
        acc.x += (v0.x + v1.x) + (v2.x + v3.x);
        acc.y += (v0.y + v1.y) + (v2.y + v3.y);
        acc.z += (v0.z + v1.z) + (v2.z + v3.z);
        acc.w += (v0.w + v1.w) + (v2.w + v3.w);
    }
    for (; e < end; e++) {
        int s = __ldg(g_csr_src + e);
        const float4 v = *reinterpret_cast<const float4*>(y + ((long long)s << 6) + lane4);
        acc.x += v.x; acc.y += v.y; acc.z += v.z; acc.w += v.w;
    }
    float di = __ldg(g_dinv + n);
    float4 x = {acc.x * di, acc.y * di, acc.z * di, acc.w * di};

    long long off = ((long long)n << 6) + lane4;
    float4* po = reinterpret_cast<float4*>(g_out + off);
    float4 o = *po;
    o.x += x.x * ALPHA; o.y += x.y * ALPHA; o.z += x.z * ALPHA; o.w += x.w * ALPHA;
    *po = o;

    if (write_next) {
        float4 yn = {x.x * di, x.y * di, x.z * di, x.w * di};
        *reinterpret_cast<float4*>(ynext + off) = yn;
    }
}

// ---------------- MLP scorer: persistent, 64-edge tiles, 4h x 4e tile ---------
// Transposed input tile sInT[dim][edge]. Per dim step per thread:
// 1 LDS.128 (W quad) + 1 LDS.128 (4 edges' x) + 16 FFMA  -> 2 B/MAC.
__global__ void __launch_bounds__(256) mlp_kernel(const int* __restrict__ lsrc,
                           const int* __restrict__ ldst,
                           const float* __restrict__ W1,   // [128,64] row-major
                           const float* __restrict__ b1,   // [64]
                           const float* __restrict__ W2,   // [64]
                           const float* __restrict__ b2,   // [1]
                           float* __restrict__ out, int npred,
                           float* __restrict__ lossp) {
    extern __shared__ float sm[];
    float* sW1  = sm + SM_W1;
    float* sInT = sm + SM_IN;
    float* sB1  = sm + SM_B1;
    float* sW2  = sm + SM_W2;
    int*   sS   = (int*)(sm + SM_S);
    int*   sD   = (int*)(sm + SM_D);

    int t = threadIdx.x;

    if (lossp && blockIdx.x == 0 && t == 0) *lossp = 0.0f;   // zero loss slot

    // cache weights once per persistent block
    for (int k = t; k < 128 * 16; k += 256)
        reinterpret_cast<float4*>(sW1)[k] = reinterpret_cast<const float4*>(W1)[k];
    if (t < 64) { sB1[t] = b1[t]; sW2[t] = W2[t]; }
    float bias2 = __ldg(b2);

    // thread tile: h4 = (t&15)*4 hidden, eb = (t>>4)*4 edges
    int h4 = (t & 15) << 2;
    int eb = (t >> 4) << 2;

    for (int tile = blockIdx.x; tile < N_MTILES; tile += gridDim.x) {
        int base = tile * MTILE;
        __syncthreads();           // protect smem reuse from previous tile
        if (t < MTILE) {
            int idx = base + t;
            int c = idx < NL ? idx : NL - 1;   // clamp tail (writes guarded)
            sS[t] = __ldg(lsrc + c);
            sD[t] = __ldg(ldst + c);
        }
        __syncthreads();

        // gather inputs transposed: item k -> edge e=k&63, quad q=k>>6 (0..31)
        for (int k = t; k < MTILE * 32; k += 256) {
            int e = k & 63;
            int q = k >> 6;
            int node = (q < 16) ? sS[e] : sD[e];
            float4 v = *reinterpret_cast<const float4*>(
                g_out + ((long long)node << 6) + ((q & 15) << 2));
            int dim = q << 2;
            sInT[(dim + 0) * EPAD + e] = v.x;
            sInT[(dim + 1) * EPAD + e] = v.y;
            sInT[(dim + 2) * EPAD + e] = v.z;
            sInT[(dim + 3) * EPAD + e] = v.w;
        }
        __syncthreads();

        // register-tiled GEMM: acc[edge][hidden], 4x4
        float acc[4][4];
#pragma unroll
        for (int e = 0; e < 4; e++)
#pragma unroll
            for (int h = 0; h < 4; h++) acc[e][h] = 0.0f;

#pragma unroll 4
        for (int i = 0; i < 128; i++) {
            float4 w  = *reinterpret_cast<const float4*>(sW1 + i * 64 + h4);
            float4 xq = *reinterpret_cast<const float4*>(sInT + i * EPAD + eb);
            float xs[4] = {xq.x, xq.y, xq.z, xq.w};
            float ws[4] = {w.x, w.y, w.z, w.w};
#pragma unroll
            for (int e = 0; e < 4; e++)
#pragma unroll
                for (int h = 0; h < 4; h++)
                    acc[e][h] = fmaf(xs[e], ws[h], acc[e][h]);
        }

        // ReLU + W2 dot per edge, reduce across 16 h-groups (lanes t&15)
        float bb[4] = {sB1[h4], sB1[h4 + 1], sB1[h4 + 2], sB1[h4 + 3]};
        float ww[4] = {sW2[h4], sW2[h4 + 1], sW2[h4 + 2], sW2[h4 + 3]};
#pragma unroll
        for (int e = 0; e < 4; e++) {
            float p = fmaxf(acc[e][0] + bb[0], 0.f) * ww[0]
                    + fmaxf(acc[e][1] + bb[1], 0.f) * ww[1]
                    + fmaxf(acc[e][2] + bb[2], 0.f) * ww[2]
                    + fmaxf(acc[e][3] + bb[3], 0.f) * ww[3];
#pragma unroll
            for (int off = 8; off > 0; off >>= 1)
                p += __shfl_down_sync(0xffffffffu, p, off, 16);
            if ((t & 15) == 0) {
                int idx = base + eb + e;
                if (idx < NL) {
                    float v = p + bias2;
                    g_pred[idx] = v;
                    if (idx < npred) out[idx] = v;
                }
            }
        }
    }
}

// ---------------- loss ---------------------------------------------------------
__global__ void loss_kernel(const float* __restrict__ label, float* __restrict__ out_loss) {
    __shared__ float sh[256];
    float acc = 0.0f;
    for (int i = blockIdx.x * blockDim.x + threadIdx.x; i < NL; i += gridDim.x * blockDim.x) {
        float diff = g_pred[i] - label[i];
        acc += diff * diff;
    }
    sh[threadIdx.x] = acc;
    __syncthreads();
    for (int stride = 128; stride > 0; stride >>= 1) {
        if (threadIdx.x < stride) sh[threadIdx.x] += sh[threadIdx.x + stride];
        __syncthreads();
    }
    if (threadIdx.x == 0) atomicAdd(out_loss, sh[0] * (1.0f / NL));
}

// ---------------- host launcher ----------------------------------------------
extern "C" void kernel_launch(void* const* d_in, const int* in_sizes, int n_in,
                              void* d_out, int out_size) {
    const int*   ei   = (const int*)d_in[0];       // [2, NE]
    const int*   eli  = (const int*)d_in[1];       // [2, NL]
    const float* elab = (const float*)d_in[2];     // [NL]
    const float* emb  = (const float*)d_in[3];     // [NN, 64]
    const float* W1   = (const float*)d_in[4];     // [128, 64]
    const float* b1   = (const float*)d_in[5];     // [64]
    const float* W2   = (const float*)d_in[6];     // [64, 1]
    const float* b2   = (const float*)d_in[7];     // [1]
    float* out = (float*)d_out;

    const int* src = ei;
    const int* dst = ei + NE;
    const int* lsrc = eli;
    const int* ldst = eli + NL;

    float *pA, *pB;
    cudaGetSymbolAddress((void**)&pA, g_A);
    cudaGetSymbolAddress((void**)&pB, g_B);

    const int T = 256;
    const int gE  = (NE + T - 1) / T;
    const int gN  = (NN + T - 1) / T;
    const int gI  = (NN * (DIM / 4) + T - 1) / T;  // init (float4 granularity)
    const int gG  = (NN * 16 + T - 1) / T;         // gather (16 lanes/node)
    const int smemBytes = SM_TOT * 4;              // ~67 KB dynamic

    static int s_attr_done = 0;
    if (!s_attr_done) {
        cudaFuncSetAttribute(mlp_kernel, cudaFuncAttributeMaxDynamicSharedMemorySize, smemBytes);
        s_attr_done = 1;
    }

    // ---- degree ----
    zero_cnt_kernel<<<gN, T>>>();
    deg_kernel<<<gE, T>>>(dst);

    // ---- CSR build (by dst); dinv fused into scan ----
    scan_block_kernel<<<NB, SCAN_B>>>();
    scan_bsum_kernel<<<1, 32>>>();
    add_offset_kernel<<<gN, T>>>();                // also re-zeros g_cnt
    fill_csr_kernel<<<gE, T>>>(src, dst);

    // ---- LightGCN: out = alpha * sum_l x^(l), pull-style gather layers ----
    init_kernel<<<gI, T>>>(emb, pA);               // out=alpha*emb; A = dinv*emb
    gather_kernel<<<gG, T>>>(pA, pB, 1);           // layer 1: A -> B (pre-scaled)
    gather_kernel<<<gG, T>>>(pB, pA, 1);           // layer 2: B -> A
    gather_kernel<<<gG, T>>>(pA, pB, 0);           // layer 3: out += only

    // ---- scorer MLP (writes g_pred and d_out; block 0 zeros the loss slot) ----
    int npred = out_size < NL ? out_size : NL;
    float* lossp = (out_size != NL) ? out + (out_size - 1) : (float*)0;
    mlp_kernel<<<MLP_BLOCKS, 256, smemBytes>>>(lsrc, ldst, W1, b1, W2, b2, out, npred, lossp);

    // ---- loss in the trailing slot (if present) ----
    if (lossp)
        loss_kernel<<<132, 256>>>(elab, lossp);
}

// round 8
// speedup vs baseline: 1.1412x; 1.0193x over previous
#include <cuda_runtime.h>

#define NN 100000          // nodes
#define DIM 64             // embed dim
#define NE 1600000         // edges
#define NL 100000          // label edges
#define ALPHA 0.25f        // 1/(NLAYERS+1), NLAYERS=3
#define SCAN_B 1024
#define NB ((NN + SCAN_B - 1) / SCAN_B)   // 98 scan blocks

// ---- MLP tiling: 64 edges/tile, 256 thr = 16 hgroups x 16 egroups x 4 edges --
#define MTILE 64
#define N_MTILES ((NL + MTILE - 1) / MTILE)   // 1563
#define MLP_BLOCKS 444     // 3 per SM, persistent
#define EPAD 68            // padded edge dimension of transposed input tile

// dynamic smem layout (floats):
// W1[8192] | sInT[128*EPAD] | b1[64] | W2[64] | sS[64 int] | sD[64 int]
#define SM_W1   0
#define SM_IN   8192
#define SM_B1   (SM_IN + 128 * EPAD)
#define SM_W2   (SM_B1 + 64)
#define SM_S    (SM_W2 + 64)
#define SM_D    (SM_S + 64)
#define SM_TOT  (SM_D + 64)                // 17152 floats = 68608 bytes

// ---------------- scratch (device globals; no allocation allowed) -------------
__device__ int   g_cnt[NN];            // degree counters
__device__ float g_dinv[NN];           // deg^-1/2
__device__ int   g_rowptr[NN + 1];     // CSR row pointers (by dst)
__device__ int   g_bsum[NB];           // scan block sums
__device__ int   g_pos[NE];            // per-edge slot within its dst row
__device__ int   g_csr_src[NE];        // CSR column indices (src nodes)
__device__ float g_A[NN * DIM];        // ping (pre-scaled y)
__device__ float g_B[NN * DIM];        // pong
__device__ float g_out[NN * DIM];      // LightGCN accumulated embedding
__device__ float g_pred[NL];           // MLP predictions

// ---------------- degree (+ slot position record) -----------------------------
__global__ void zero_cnt_kernel() {
    int i = blockIdx.x * blockDim.x + threadIdx.x;
    if (i < NN) g_cnt[i] = 0;
}

__global__ void deg_kernel(const int* __restrict__ dst) {
    int e = blockIdx.x * blockDim.x + threadIdx.x;
    if (e < NE) g_pos[e] = atomicAdd(&g_cnt[dst[e]], 1);
}

// ---------------- CSR build: prefix sum (+dinv fused) + atomic-free fill ------
__global__ void scan_block_kernel() {
    __shared__ int sh[SCAN_B];
    int i = blockIdx.x * SCAN_B + threadIdx.x;
    int v = (i < NN) ? g_cnt[i] : 0;
    if (i < NN) g_dinv[i] = (v > 0) ? rsqrtf((float)v) : 0.0f;   // fused dinv
    sh[threadIdx.x] = v;
    __syncthreads();
#pragma unroll
    for (int off = 1; off < SCAN_B; off <<= 1) {
        int t = 0;
        if (threadIdx.x >= off) t = sh[threadIdx.x - off];
        __syncthreads();
        if (threadIdx.x >= off) sh[threadIdx.x] += t;
        __syncthreads();
    }
    if (i < NN) g_rowptr[i] = sh[threadIdx.x] - v;   // exclusive within block
    if (threadIdx.x == SCAN_B - 1) g_bsum[blockIdx.x] = sh[SCAN_B - 1];
}

// parallel block-scan over the 98 block sums (was a serial 1-thread loop)
__global__ void scan_bsum_kernel() {
    __shared__ int sh[128];
    int t = threadIdx.x;
    int v = (t < NB) ? g_bsum[t] : 0;
    sh[t] = v;
    __syncthreads();
#pragma unroll
    for (int off = 1; off < 128; off <<= 1) {
        int u = 0;
        if (t >= off) u = sh[t - off];
        __syncthreads();
        if (t >= off) sh[t] += u;
        __syncthreads();
    }
    if (t < NB) g_bsum[t] = sh[t] - v;               // exclusive
}

__global__ void add_offset_kernel() {
    int i = blockIdx.x * blockDim.x + threadIdx.x;
    if (i < NN) g_rowptr[i] += g_bsum[i >> 10];
    if (i == 0) g_rowptr[NN] = NE;
}

__global__ void fill_csr_kernel(const int* __restrict__ src, const int* __restrict__ dst) {
    int e = blockIdx.x * blockDim.x + threadIdx.x;
    if (e < NE)
        g_csr_src[g_rowptr[dst[e]] + g_pos[e]] = src[e];   // no atomics
}

// ---------------- init: out = alpha*emb; y0 = dinv * emb ----------------------
__global__ void init_kernel(const float* __restrict__ emb, float* __restrict__ y) {
    int i = blockIdx.x * blockDim.x + threadIdx.x;   // float4 index
    if (i >= NN * (DIM / 4)) return;
    int n = i >> 4;
    float di = __ldg(g_dinv + n);
    float4 v = reinterpret_cast<const float4*>(emb)[i];
    float4 o = {v.x * ALPHA, v.y * ALPHA, v.z * ALPHA, v.w * ALPHA};
    reinterpret_cast<float4*>(g_out)[i] = o;
    float4 s = {v.x * di, v.y * di, v.z * di, v.w * di};
    reinterpret_cast<float4*>(y)[i] = s;
}

// ---------------- gather layer ------------------------------------------------
// 16 lanes per node; lane owns one float4 column chunk. Edge loop unrolled x4.
// Thread 0 also zeroes the loss slot on the final layer (lossp != 0 then).
__global__ void __launch_bounds__(256) gather_kernel(const float* __restrict__ y,
                                                     float* __restrict__ ynext,
                                                     int write_next,
                                                     float* __restrict__ lossp) {
    int idx = blockIdx.x * blockDim.x + threadIdx.x;
    if (lossp && idx == 0) *lossp = 0.0f;
    int n = idx >> 4;
    if (n >= NN) return;
    int lane4 = (idx & 15) << 2;   // float offset within row

    int beg = __ldg(g_rowptr + n);
    int end = __ldg(g_rowptr + n + 1);

    float4 acc = {0.0f, 0.0f, 0.0f, 0.0f};
    int e = beg;
    for (; e + 4 <= end; e += 4) {
        int s0 = __ldg(g_csr_src + e + 0);
        int s1 = __ldg(g_csr_src + e + 1);
        int s2 = __ldg(g_csr_src + e + 2);
        int s3 = __ldg(g_csr_src + e + 3);
        float4 v0 = *reinterpret_cast<const float4*>(y + ((long long)s0 << 6) + lane4);
        float4 v1 = *reinterpret_cast<const float4*>(y + ((long long)s1 << 6) + lane4);
        float4 v2 = *reinterpret_cast<const float4*>(y + ((long long)s2 << 6) + lane4);
        float4 v3 = *reinterpret_cast<const float4*>(y + ((long long)s3 << 6) + lane4);
        acc.x += (v0.x + v1.x) + (v2.x + v3.x);
        acc.y += (v0.y + v1.y) + (v2.y + v3.y);
        acc.z += (v0.z + v1.z) + (v2.z + v3.z);
        acc.w += (v0.w + v1.w) + (v2.w + v3.w);
    }
    for (; e < end; e++) {
        int s = __ldg(g_csr_src + e);
        const float4 v = *reinterpret_cast<const float4*>(y + ((long long)s << 6) + lane4);
        acc.x += v.x; acc.y += v.y; acc.z += v.z; acc.w += v.w;
    }
    float di = __ldg(g_dinv + n);
    float4 x = {acc.x * di, acc.y * di, acc.z * di, acc.w * di};

    long long off = ((long long)n << 6) + lane4;
    float4* po = reinterpret_cast<float4*>(g_out + off);
    float4 o = *po;
    o.x += x.x * ALPHA; o.y += x.y * ALPHA; o.z += x.z * ALPHA; o.w += x.w * ALPHA;
    *po = o;

    if (write_next) {
        float4 yn = {x.x * di, x.y * di, x.z * di, x.w * di};
        *reinterpret_cast<float4*>(ynext + off) = yn;
    }
}

// ---------------- MLP scorer: persistent, 64-edge tiles, 4h x 4e tile ---------
// Also accumulates the MSE loss (one atomic per block at exit).
__global__ void __launch_bounds__(256) mlp_kernel(const int* __restrict__ lsrc,
                           const int* __restrict__ ldst,
                           const float* __restrict__ W1,   // [128,64] row-major
                           const float* __restrict__ b1,   // [64]
                           const float* __restrict__ W2,   // [64]
                           const float* __restrict__ b2,   // [1]
                           const float* __restrict__ label,
                           float* __restrict__ out, int npred,
                           float* __restrict__ lossp) {
    extern __shared__ float sm[];
    float* sW1  = sm + SM_W1;
    float* sInT = sm + SM_IN;
    float* sB1  = sm + SM_B1;
    float* sW2  = sm + SM_W2;
    int*   sS   = (int*)(sm + SM_S);
    int*   sD   = (int*)(sm + SM_D);

    int t = threadIdx.x;

    // cache weights once per persistent block
    for (int k = t; k < 128 * 16; k += 256)
        reinterpret_cast<float4*>(sW1)[k] = reinterpret_cast<const float4*>(W1)[k];
    if (t < 64) { sB1[t] = b1[t]; sW2[t] = W2[t]; }
    float bias2 = __ldg(b2);

    // thread tile: h4 = (t&15)*4 hidden, eb = (t>>4)*4 edges
    int h4 = (t & 15) << 2;
    int eb = (t >> 4) << 2;

    float lsum = 0.0f;   // local (pred - label)^2 accumulator

    for (int tile = blockIdx.x; tile < N_MTILES; tile += gridDim.x) {
        int base = tile * MTILE;
        __syncthreads();           // protect smem reuse from previous tile
        if (t < MTILE) {
            int idx = base + t;
            int c = idx < NL ? idx : NL - 1;   // clamp tail (writes guarded)
            sS[t] = __ldg(lsrc + c);
            sD[t] = __ldg(ldst + c);
        }
        __syncthreads();

        // gather inputs transposed: item k -> edge e=k&63, quad q=k>>6 (0..31)
        for (int k = t; k < MTILE * 32; k += 256) {
            int e = k & 63;
            int q = k >> 6;
            int node = (q < 16) ? sS[e] : sD[e];
            float4 v = *reinterpret_cast<const float4*>(
                g_out + ((long long)node << 6) + ((q & 15) << 2));
            int dim = q << 2;
            sInT[(dim + 0) * EPAD + e] = v.x;
            sInT[(dim + 1) * EPAD + e] = v.y;
            sInT[(dim + 2) * EPAD + e] = v.z;
            sInT[(dim + 3) * EPAD + e] = v.w;
        }
        __syncthreads();

        // register-tiled GEMM: acc[edge][hidden], 4x4
        float acc[4][4];
#pragma unroll
        for (int e = 0; e < 4; e++)
#pragma unroll
            for (int h = 0; h < 4; h++) acc[e][h] = 0.0f;

#pragma unroll 4
        for (int i = 0; i < 128; i++) {
            float4 w  = *reinterpret_cast<const float4*>(sW1 + i * 64 + h4);
            float4 xq = *reinterpret_cast<const float4*>(sInT + i * EPAD + eb);
            float xs[4] = {xq.x, xq.y, xq.z, xq.w};
            float ws[4] = {w.x, w.y, w.z, w.w};
#pragma unroll
            for (int e = 0; e < 4; e++)
#pragma unroll
                for (int h = 0; h < 4; h++)
                    acc[e][h] = fmaf(xs[e], ws[h], acc[e][h]);
        }

        // ReLU + W2 dot per edge, reduce across 16 h-groups (lanes t&15)
        float bb[4] = {sB1[h4], sB1[h4 + 1], sB1[h4 + 2], sB1[h4 + 3]};
        float ww[4] = {sW2[h4], sW2[h4 + 1], sW2[h4 + 2], sW2[h4 + 3]};
#pragma unroll
        for (int e = 0; e < 4; e++) {
            float p = fmaxf(acc[e][0] + bb[0], 0.f) * ww[0]
                    + fmaxf(acc[e][1] + bb[1], 0.f) * ww[1]
                    + fmaxf(acc[e][2] + bb[2], 0.f) * ww[2]
                    + fmaxf(acc[e][3] + bb[3], 0.f) * ww[3];
#pragma unroll
            for (int off = 8; off > 0; off >>= 1)
                p += __shfl_down_sync(0xffffffffu, p, off, 16);
            if ((t & 15) == 0) {
                int idx = base + eb + e;
                if (idx < NL) {
                    float v = p + bias2;
                    g_pred[idx] = v;
                    if (idx < npred) out[idx] = v;
                    if (lossp) {
                        float diff = v - __ldg(label + idx);
                        lsum += diff * diff;
                    }
                }
            }
        }
    }

    // block-reduce loss partials; one atomic per block
    if (lossp) {
        __syncthreads();
        sInT[t] = lsum;        // reuse smem
        __syncthreads();
        for (int stride = 128; stride > 0; stride >>= 1) {
            if (t < stride) sInT[t] += sInT[t + stride];
            __syncthreads();
        }
        if (t == 0) atomicAdd(lossp, sInT[0] * (1.0f / NL));
    }
}

// ---------------- host launcher ----------------------------------------------
extern "C" void kernel_launch(void* const* d_in, const int* in_sizes, int n_in,
                              void* d_out, int out_size) {
    const int*   ei   = (const int*)d_in[0];       // [2, NE]
    const int*   eli  = (const int*)d_in[1];       // [2, NL]
    const float* elab = (const float*)d_in[2];     // [NL]
    const float* emb  = (const float*)d_in[3];     // [NN, 64]
    const float* W1   = (const float*)d_in[4];     // [128, 64]
    const float* b1   = (const float*)d_in[5];     // [64]
    const float* W2   = (const float*)d_in[6];     // [64, 1]
    const float* b2   = (const float*)d_in[7];     // [1]
    float* out = (float*)d_out;

    const int* src = ei;
    const int* dst = ei + NE;
    const int* lsrc = eli;
    const int* ldst = eli + NL;

    float *pA, *pB;
    cudaGetSymbolAddress((void**)&pA, g_A);
    cudaGetSymbolAddress((void**)&pB, g_B);

    const int T = 256;
    const int gE  = (NE + T - 1) / T;
    const int gN  = (NN + T - 1) / T;
    const int gI  = (NN * (DIM / 4) + T - 1) / T;  // init (float4 granularity)
    const int gG  = (NN * 16 + T - 1) / T;         // gather (16 lanes/node)
    const int smemBytes = SM_TOT * 4;              // ~67 KB dynamic

    static int s_attr_done = 0;
    if (!s_attr_done) {
        cudaFuncSetAttribute(mlp_kernel, cudaFuncAttributeMaxDynamicSharedMemorySize, smemBytes);
        s_attr_done = 1;
    }

    int npred = out_size < NL ? out_size : NL;
    float* lossp = (out_size != NL) ? out + (out_size - 1) : (float*)0;

    // ---- degree (records per-edge slot positions) ----
    zero_cnt_kernel<<<gN, T>>>();
    deg_kernel<<<gE, T>>>(dst);

    // ---- CSR build (by dst); dinv fused into scan; fill is atomic-free ----
    scan_block_kernel<<<NB, SCAN_B>>>();
    scan_bsum_kernel<<<1, 128>>>();
    add_offset_kernel<<<gN, T>>>();
    fill_csr_kernel<<<gE, T>>>(src, dst);

    // ---- LightGCN: out = alpha * sum_l x^(l), pull-style gather layers ----
    init_kernel<<<gI, T>>>(emb, pA);               // out=alpha*emb; A = dinv*emb
    gather_kernel<<<gG, T>>>(pA, pB, 1, (float*)0);    // layer 1
    gather_kernel<<<gG, T>>>(pB, pA, 1, (float*)0);    // layer 2
    gather_kernel<<<gG, T>>>(pA, pB, 0, lossp);        // layer 3 (+zero loss slot)

    // ---- scorer MLP (writes g_pred, d_out, and fused MSE loss) ----
    mlp_kernel<<<MLP_BLOCKS, 256, smemBytes>>>(lsrc, ldst, W1, b1, W2, b2,
                                               elab, out, npred, lossp);
}

// round 9
// speedup vs baseline: 1.2922x; 1.1323x over previous
#include <cuda_runtime.h>
#include <cuda_fp16.h>

#define NN 100000          // nodes
#define DIM 64             // embed dim
#define NE 1600000         // edges
#define NL 100000          // label edges
#define ALPHA 0.25f        // 1/(NLAYERS+1), NLAYERS=3
#define SCAN_B 1024
#define NB ((NN + SCAN_B - 1) / SCAN_B)   // 98 scan blocks

// ---- MLP tiling: 64 edges/tile, 256 thr = 16 hgroups x 16 egroups x 4 edges --
#define MTILE 64
#define N_MTILES ((NL + MTILE - 1) / MTILE)   // 1563
#define MLP_BLOCKS 444     // 3 per SM, persistent
#define EPAD 68            // padded edge dimension of transposed input tile

// dynamic smem layout (floats):
// W1[8192] | sInT[128*EPAD] | b1[64] | W2[64] | sS[64 int] | sD[64 int]
#define SM_W1   0
#define SM_IN   8192
#define SM_B1   (SM_IN + 128 * EPAD)
#define SM_W2   (SM_B1 + 64)
#define SM_S    (SM_W2 + 64)
#define SM_D    (SM_S + 64)
#define SM_TOT  (SM_D + 64)                // 17152 floats = 68608 bytes

// ---------------- scratch (device globals; no allocation allowed) -------------
__device__ int    g_cnt[NN];           // degree counters
__device__ float  g_dinv[NN];          // deg^-1/2
__device__ int    g_rowptr[NN + 1];    // CSR row pointers (by dst)
__device__ int    g_bsum[NB];          // scan block sums
__device__ int    g_pos[NE];           // per-edge slot within its dst row
__device__ int    g_csr_src[NE];       // CSR column indices (src nodes)
__device__ __half g_Ah[NN * DIM];      // ping (pre-scaled y, fp16)
__device__ __half g_Bh[NN * DIM];      // pong (fp16)
__device__ float  g_out[NN * DIM];     // LightGCN accumulated embedding (fp32)
__device__ float  g_pred[NL];          // MLP predictions

// ---------------- degree (+ slot position record) -----------------------------
__global__ void zero_cnt_kernel() {
    int i = blockIdx.x * blockDim.x + threadIdx.x;
    if (i < NN) g_cnt[i] = 0;
}

__global__ void deg_kernel(const int* __restrict__ dst) {
    int e = blockIdx.x * blockDim.x + threadIdx.x;
    if (e < NE) g_pos[e] = atomicAdd(&g_cnt[dst[e]], 1);
}

// ---------------- CSR build: prefix sum (+dinv fused) + atomic-free fill ------
__global__ void scan_block_kernel() {
    __shared__ int sh[SCAN_B];
    int i = blockIdx.x * SCAN_B + threadIdx.x;
    int v = (i < NN) ? g_cnt[i] : 0;
    if (i < NN) g_dinv[i] = (v > 0) ? rsqrtf((float)v) : 0.0f;   // fused dinv
    sh[threadIdx.x] = v;
    __syncthreads();
#pragma unroll
    for (int off = 1; off < SCAN_B; off <<= 1) {
        int t = 0;
        if (threadIdx.x >= off) t = sh[threadIdx.x - off];
        __syncthreads();
        if (threadIdx.x >= off) sh[threadIdx.x] += t;
        __syncthreads();
    }
    if (i < NN) g_rowptr[i] = sh[threadIdx.x] - v;   // exclusive within block
    if (threadIdx.x == SCAN_B - 1) g_bsum[blockIdx.x] = sh[SCAN_B - 1];
}

__global__ void scan_bsum_kernel() {
    __shared__ int sh[128];
    int t = threadIdx.x;
    int v = (t < NB) ? g_bsum[t] : 0;
    sh[t] = v;
    __syncthreads();
#pragma unroll
    for (int off = 1; off < 128; off <<= 1) {
        int u = 0;
        if (t >= off) u = sh[t - off];
        __syncthreads();
        if (t >= off) sh[t] += u;
        __syncthreads();
    }
    if (t < NB) g_bsum[t] = sh[t] - v;               // exclusive
}

__global__ void add_offset_kernel() {
    int i = blockIdx.x * blockDim.x + threadIdx.x;
    if (i < NN) g_rowptr[i] += g_bsum[i >> 10];
    if (i == 0) g_rowptr[NN] = NE;
}

__global__ void fill_csr_kernel(const int* __restrict__ src, const int* __restrict__ dst) {
    int e = blockIdx.x * blockDim.x + threadIdx.x;
    if (e < NE)
        g_csr_src[g_rowptr[dst[e]] + g_pos[e]] = src[e];   // no atomics
}

// ---------------- init: out = alpha*emb; y0 = fp16(dinv * emb) -----------------
// One thread per 8-dim group.
__global__ void init_kernel(const float* __restrict__ emb, __half* __restrict__ y) {
    int idx = blockIdx.x * blockDim.x + threadIdx.x;
    if (idx >= NN * 8) return;
    int n = idx >> 3;
    int off8 = (idx & 7) << 3;                       // float offset (8 dims)
    float di = __ldg(g_dinv + n);
    long long base = ((long long)n << 6) + off8;

    float4 v0 = *reinterpret_cast<const float4*>(emb + base);
    float4 v1 = *reinterpret_cast<const float4*>(emb + base + 4);

    float4 o0 = {v0.x * ALPHA, v0.y * ALPHA, v0.z * ALPHA, v0.w * ALPHA};
    float4 o1 = {v1.x * ALPHA, v1.y * ALPHA, v1.z * ALPHA, v1.w * ALPHA};
    *reinterpret_cast<float4*>(g_out + base)     = o0;
    *reinterpret_cast<float4*>(g_out + base + 4) = o1;

    half2 h[4];
    h[0] = __floats2half2_rn(v0.x * di, v0.y * di);
    h[1] = __floats2half2_rn(v0.z * di, v0.w * di);
    h[2] = __floats2half2_rn(v1.x * di, v1.y * di);
    h[3] = __floats2half2_rn(v1.z * di, v1.w * di);
    *reinterpret_cast<uint4*>(y + base) = *reinterpret_cast<uint4*>(h);
}

// ---------------- gather layer (fp16 messages, fp32 accumulation) --------------
// 8 lanes per node; lane owns 8 dims (16B fp16). A node row is one 128B line.
__global__ void __launch_bounds__(256) gather_kernel(const __half* __restrict__ y,
                                                     __half* __restrict__ ynext,
                                                     int write_next,
                                                     float* __restrict__ lossp) {
    int idx = blockIdx.x * blockDim.x + threadIdx.x;
    if (lossp && idx == 0) *lossp = 0.0f;
    int n = idx >> 3;
    if (n >= NN) return;
    int lane8 = (idx & 7) << 3;    // half offset within 64-dim row

    int beg = __ldg(g_rowptr + n);
    int end = __ldg(g_rowptr + n + 1);

    float acc[8] = {0.f, 0.f, 0.f, 0.f, 0.f, 0.f, 0.f, 0.f};

    int e = beg;
    for (; e + 4 <= end; e += 4) {
        int s0 = __ldg(g_csr_src + e + 0);
        int s1 = __ldg(g_csr_src + e + 1);
        int s2 = __ldg(g_csr_src + e + 2);
        int s3 = __ldg(g_csr_src + e + 3);
        uint4 r0 = *reinterpret_cast<const uint4*>(y + ((long long)s0 << 6) + lane8);
        uint4 r1 = *reinterpret_cast<const uint4*>(y + ((long long)s1 << 6) + lane8);
        uint4 r2 = *reinterpret_cast<const uint4*>(y + ((long long)s2 << 6) + lane8);
        uint4 r3 = *reinterpret_cast<const uint4*>(y + ((long long)s3 << 6) + lane8);
        const half2* h0 = reinterpret_cast<const half2*>(&r0);
        const half2* h1 = reinterpret_cast<const half2*>(&r1);
        const half2* h2 = reinterpret_cast<const half2*>(&r2);
        const half2* h3 = reinterpret_cast<const half2*>(&r3);
#pragma unroll
        for (int k = 0; k < 4; k++) {
            float2 f0 = __half22float2(h0[k]);
            float2 f1 = __half22float2(h1[k]);
            float2 f2 = __half22float2(h2[k]);
            float2 f3 = __half22float2(h3[k]);
            acc[2 * k]     += (f0.x + f1.x) + (f2.x + f3.x);
            acc[2 * k + 1] += (f0.y + f1.y) + (f2.y + f3.y);
        }
    }
    for (; e < end; e++) {
        int s = __ldg(g_csr_src + e);
        uint4 r = *reinterpret_cast<const uint4*>(y + ((long long)s << 6) + lane8);
        const half2* h = reinterpret_cast<const half2*>(&r);
#pragma unroll
        for (int k = 0; k < 4; k++) {
            float2 f = __half22float2(h[k]);
            acc[2 * k]     += f.x;
            acc[2 * k + 1] += f.y;
        }
    }

    float di = __ldg(g_dinv + n);
    long long base = ((long long)n << 6) + lane8;

    // x = acc * di; out += alpha * x (fp32 RMW)
    float x[8];
#pragma unroll
    for (int k = 0; k < 8; k++) x[k] = acc[k] * di;

    float4* po0 = reinterpret_cast<float4*>(g_out + base);
    float4* po1 = reinterpret_cast<float4*>(g_out + base + 4);
    float4 o0 = *po0, o1 = *po1;
    o0.x += x[0] * ALPHA; o0.y += x[1] * ALPHA; o0.z += x[2] * ALPHA; o0.w += x[3] * ALPHA;
    o1.x += x[4] * ALPHA; o1.y += x[5] * ALPHA; o1.z += x[6] * ALPHA; o1.w += x[7] * ALPHA;
    *po0 = o0; *po1 = o1;

    if (write_next) {
        half2 h[4];
        h[0] = __floats2half2_rn(x[0] * di, x[1] * di);
        h[1] = __floats2half2_rn(x[2] * di, x[3] * di);
        h[2] = __floats2half2_rn(x[4] * di, x[5] * di);
        h[3] = __floats2half2_rn(x[6] * di, x[7] * di);
        *reinterpret_cast<uint4*>(ynext + base) = *reinterpret_cast<uint4*>(h);
    }
}

// ---------------- MLP scorer: persistent, 64-edge tiles, 4h x 4e tile ---------
// Also accumulates the MSE loss (one atomic per block at exit).
__global__ void __launch_bounds__(256) mlp_kernel(const int* __restrict__ lsrc,
                           const int* __restrict__ ldst,
                           const float* __restrict__ W1,   // [128,64] row-major
                           const float* __restrict__ b1,   // [64]
                           const float* __restrict__ W2,   // [64]
                           const float* __restrict__ b2,   // [1]
                           const float* __restrict__ label,
                           float* __restrict__ out, int npred,
                           float* __restrict__ lossp) {
    extern __shared__ float sm[];
    float* sW1  = sm + SM_W1;
    float* sInT = sm + SM_IN;
    float* sB1  = sm + SM_B1;
    float* sW2  = sm + SM_W2;
    int*   sS   = (int*)(sm + SM_S);
    int*   sD   = (int*)(sm + SM_D);

    int t = threadIdx.x;

    // cache weights once per persistent block
    for (int k = t; k < 128 * 16; k += 256)
        reinterpret_cast<float4*>(sW1)[k] = reinterpret_cast<const float4*>(W1)[k];
    if (t < 64) { sB1[t] = b1[t]; sW2[t] = W2[t]; }
    float bias2 = __ldg(b2);

    // thread tile: h4 = (t&15)*4 hidden, eb = (t>>4)*4 edges
    int h4 = (t & 15) << 2;
    int eb = (t >> 4) << 2;

    float lsum = 0.0f;   // local (pred - label)^2 accumulator

    for (int tile = blockIdx.x; tile < N_MTILES; tile += gridDim.x) {
        int base = tile * MTILE;
        __syncthreads();           // protect smem reuse from previous tile
        if (t < MTILE) {
            int idx = base + t;
            int c = idx < NL ? idx : NL - 1;   // clamp tail (writes guarded)
            sS[t] = __ldg(lsrc + c);
            sD[t] = __ldg(ldst + c);
        }
        __syncthreads();

        // gather inputs transposed: item k -> edge e=k&63, quad q=k>>6 (0..31)
        for (int k = t; k < MTILE * 32; k += 256) {
            int e = k & 63;
            int q = k >> 6;
            int node = (q < 16) ? sS[e] : sD[e];
            float4 v = *reinterpret_cast<const float4*>(
                g_out + ((long long)node << 6) + ((q & 15) << 2));
            int dim = q << 2;
            sInT[(dim + 0) * EPAD + e] = v.x;
            sInT[(dim + 1) * EPAD + e] = v.y;
            sInT[(dim + 2) * EPAD + e] = v.z;
            sInT[(dim + 3) * EPAD + e] = v.w;
        }
        __syncthreads();

        // register-tiled GEMM: acc[edge][hidden], 4x4
        float acc[4][4];
#pragma unroll
        for (int e = 0; e < 4; e++)
#pragma unroll
            for (int h = 0; h < 4; h++) acc[e][h] = 0.0f;

#pragma unroll 4
        for (int i = 0; i < 128; i++) {
            float4 w  = *reinterpret_cast<const float4*>(sW1 + i * 64 + h4);
            float4 xq = *reinterpret_cast<const float4*>(sInT + i * EPAD + eb);
            float xs[4] = {xq.x, xq.y, xq.z, xq.w};
            float ws[4] = {w.x, w.y, w.z, w.w};
#pragma unroll
            for (int e = 0; e < 4; e++)
#pragma unroll
                for (int h = 0; h < 4; h++)
                    acc[e][h] = fmaf(xs[e], ws[h], acc[e][h]);
        }

        // ReLU + W2 dot per edge, reduce across 16 h-groups (lanes t&15)
        float bb[4] = {sB1[h4], sB1[h4 + 1], sB1[h4 + 2], sB1[h4 + 3]};
        float ww[4] = {sW2[h4], sW2[h4 + 1], sW2[h4 + 2], sW2[h4 + 3]};
#pragma unroll
        for (int e = 0; e < 4; e++) {
            float p = fmaxf(acc[e][0] + bb[0], 0.f) * ww[0]
                    + fmaxf(acc[e][1] + bb[1], 0.f) * ww[1]
                    + fmaxf(acc[e][2] + bb[2], 0.f) * ww[2]
                    + fmaxf(acc[e][3] + bb[3], 0.f) * ww[3];
#pragma unroll
            for (int off = 8; off > 0; off >>= 1)
                p += __shfl_down_sync(0xffffffffu, p, off, 16);
            if ((t & 15) == 0) {
                int idx = base + eb + e;
                if (idx < NL) {
                    float v = p + bias2;
                    g_pred[idx] = v;
                    if (idx < npred) out[idx] = v;
                    if (lossp) {
                        float diff = v - __ldg(label + idx);
                        lsum += diff * diff;
                    }
                }
            }
        }
    }

    // block-reduce loss partials; one atomic per block
    if (lossp) {
        __syncthreads();
        sInT[t] = lsum;        // reuse smem
        __syncthreads();
        for (int stride = 128; stride > 0; stride >>= 1) {
            if (t < stride) sInT[t] += sInT[t + stride];
            __syncthreads();
        }
        if (t == 0) atomicAdd(lossp, sInT[0] * (1.0f / NL));
    }
}

// ---------------- host launcher ----------------------------------------------
extern "C" void kernel_launch(void* const* d_in, const int* in_sizes, int n_in,
                              void* d_out, int out_size) {
    const int*   ei   = (const int*)d_in[0];       // [2, NE]
    const int*   eli  = (const int*)d_in[1];       // [2, NL]
    const float* elab = (const float*)d_in[2];     // [NL]
    const float* emb  = (const float*)d_in[3];     // [NN, 64]
    const float* W1   = (const float*)d_in[4];     // [128, 64]
    const float* b1   = (const float*)d_in[5];     // [64]
    const float* W2   = (const float*)d_in[6];     // [64, 1]
    const float* b2   = (const float*)d_in[7];     // [1]
    float* out = (float*)d_out;

    const int* src = ei;
    const int* dst = ei + NE;
    const int* lsrc = eli;
    const int* ldst = eli + NL;

    __half *pA, *pB;
    cudaGetSymbolAddress((void**)&pA, g_Ah);
    cudaGetSymbolAddress((void**)&pB, g_Bh);

    const int T = 256;
    const int gE  = (NE + T - 1) / T;
    const int gN  = (NN + T - 1) / T;
    const int g8  = (NN * 8 + T - 1) / T;          // init/gather (8 lanes/node)
    const int smemBytes = SM_TOT * 4;              // ~67 KB dynamic

    static int s_attr_done = 0;
    if (!s_attr_done) {
        cudaFuncSetAttribute(mlp_kernel, cudaFuncAttributeMaxDynamicSharedMemorySize, smemBytes);
        s_attr_done = 1;
    }

    int npred = out_size < NL ? out_size : NL;
    float* lossp = (out_size != NL) ? out + (out_size - 1) : (float*)0;

    // ---- degree (records per-edge slot positions) ----
    zero_cnt_kernel<<<gN, T>>>();
    deg_kernel<<<gE, T>>>(dst);

    // ---- CSR build (by dst); dinv fused into scan; fill is atomic-free ----
    scan_block_kernel<<<NB, SCAN_B>>>();
    scan_bsum_kernel<<<1, 128>>>();
    add_offset_kernel<<<gN, T>>>();
    fill_csr_kernel<<<gE, T>>>(src, dst);

    // ---- LightGCN: out = alpha * sum_l x^(l), fp16 message gather layers ----
    init_kernel<<<g8, T>>>(emb, pA);                   // out=alpha*emb; A=h(dinv*emb)
    gather_kernel<<<g8, T>>>(pA, pB, 1, (float*)0);    // layer 1
    gather_kernel<<<g8, T>>>(pB, pA, 1, (float*)0);    // layer 2
    gather_kernel<<<g8, T>>>(pA, pB, 0, lossp);        // layer 3 (+zero loss slot)

    // ---- scorer MLP (writes g_pred, d_out, and fused MSE loss) ----
    mlp_kernel<<<MLP_BLOCKS, 256, smemBytes>>>(lsrc, ldst, W1, b1, W2, b2,
                                               elab, out, npred, lossp);
}